// round 3
// baseline (speedup 1.0000x reference)
#include <cuda_runtime.h>
#include <math.h>

#define BATCH 4
#define CH    512
#define LEN   2048

__device__ float g_yq[BATCH*CH*LEN];
__device__ float g_yk[BATCH*CH*LEN];
__device__ float g_yv[BATCH*CH*LEN];
__device__ float g_z [BATCH*CH*LEN];

// ---- packed fp32x2 helpers (Blackwell FFMA2 path; fp32-exact) ---------------
typedef unsigned long long ull;

__device__ __forceinline__ ull f2_dup(float x) {
    ull r; asm("mov.b64 %0, {%1, %1};" : "=l"(r) : "f"(x)); return r;
}
__device__ __forceinline__ ull f2_pack(float x, float y) {
    ull r; asm("mov.b64 %0, {%1, %2};" : "=l"(r) : "f"(x), "f"(y)); return r;
}
__device__ __forceinline__ void f2_fma(ull& d, ull a, ull b) {
    asm("fma.rn.f32x2 %0, %1, %2, %0;" : "+l"(d) : "l"(a), "l"(b));
}
__device__ __forceinline__ void f2_mul(ull& d, ull a) {
    asm("mul.rn.f32x2 %0, %0, %1;" : "+l"(d) : "l"(a));
}
__device__ __forceinline__ float2 f2_unpack(ull v) {
    float2 f; asm("mov.b64 {%0, %1}, %2;" : "=f"(f.x), "=f"(f.y) : "l"(v)); return f;
}

// ---------------------------------------------------------------------------
// Conv1d (k=3, same). Tile: 64 co x 128 pos, 256 threads, 4x8 micro, FFMA2.
// Accumulator pairs run over the co dimension (W pairs direct from LDS.128).
// ---------------------------------------------------------------------------
__device__ __forceinline__
void conv_body(const float* __restrict__ x, const float* __restrict__ w,
               const float* __restrict__ bias, float* __restrict__ y,
               int b, int co0, int l0)
{
    __shared__ float Ws[48][68];    // [ci*3+t][co]   pitch 68 -> 16B-aligned rows
    __shared__ float Xs[16][132];   // [ci][l0-1 .. l0+128]

    const int tid = threadIdx.x;
    const int tx = tid & 15, ty = tid >> 4;
    const float* xb = x + (size_t)b * (CH * LEN);

    ull acc[2][8];                  // [co-pair][pos], each = 2 co lanes
    #pragma unroll
    for (int p = 0; p < 2; p++)
        #pragma unroll
        for (int c = 0; c < 8; c++) acc[p][c] = 0ull;

    for (int ci0 = 0; ci0 < CH; ci0 += 16) {
        __syncthreads();
        for (int idx = tid; idx < 16 * 130; idx += 256) {
            int r = idx / 130, c = idx - r * 130;
            int gl = l0 - 1 + c;
            Xs[r][c] = (gl >= 0 && gl < LEN) ? xb[(ci0 + r) * LEN + gl] : 0.f;
        }
        for (int idx = tid; idx < 48 * 64; idx += 256) {
            int r = idx >> 6, co = idx & 63;          // conflict-free stores
            Ws[r][co] = w[(size_t)(co0 + co) * (CH * 3) + ci0 * 3 + r];
        }
        __syncthreads();

        #pragma unroll 4
        for (int ci = 0; ci < 16; ci++) {
            // 10-float X window for 8 outputs x 3 taps, dup-packed once
            float4 xa = *(const float4*)&Xs[ci][(tx << 3)];
            float4 xb4 = *(const float4*)&Xs[ci][(tx << 3) + 4];
            float2 xc2 = *(const float2*)&Xs[ci][(tx << 3) + 8];
            ull xd[10];
            xd[0] = f2_dup(xa.x);  xd[1] = f2_dup(xa.y);
            xd[2] = f2_dup(xa.z);  xd[3] = f2_dup(xa.w);
            xd[4] = f2_dup(xb4.x); xd[5] = f2_dup(xb4.y);
            xd[6] = f2_dup(xb4.z); xd[7] = f2_dup(xb4.w);
            xd[8] = f2_dup(xc2.x); xd[9] = f2_dup(xc2.y);
            #pragma unroll
            for (int t = 0; t < 3; t++) {
                float4 w4 = *(const float4*)&Ws[ci * 3 + t][ty << 2];
                ull wp0 = f2_pack(w4.x, w4.y);
                ull wp1 = f2_pack(w4.z, w4.w);
                #pragma unroll
                for (int c = 0; c < 8; c++) {
                    f2_fma(acc[0][c], wp0, xd[c + t]);
                    f2_fma(acc[1][c], wp1, xd[c + t]);
                }
            }
        }
    }

    #pragma unroll
    for (int p = 0; p < 2; p++) {
        int co = co0 + (ty << 2) + (p << 1);
        float bv0 = bias[co], bv1 = bias[co + 1];
        float r0[8], r1[8];
        #pragma unroll
        for (int c = 0; c < 8; c++) {
            float2 u = f2_unpack(acc[p][c]);
            r0[c] = u.x + bv0;
            r1[c] = u.y + bv1;
        }
        float* y0 = y + ((size_t)b * CH + co) * LEN + l0 + (tx << 3);
        *(float4*)(y0)         = make_float4(r0[0], r0[1], r0[2], r0[3]);
        *(float4*)(y0 + 4)     = make_float4(r0[4], r0[5], r0[6], r0[7]);
        *(float4*)(y0 + LEN)   = make_float4(r1[0], r1[1], r1[2], r1[3]);
        *(float4*)(y0 + LEN+4) = make_float4(r1[4], r1[5], r1[6], r1[7]);
    }
}

__global__ __launch_bounds__(256)
void conv_qkv_k(const float* __restrict__ q, const float* __restrict__ k,
                const float* __restrict__ v,
                const float* __restrict__ wq, const float* __restrict__ wk,
                const float* __restrict__ wv,
                const float* __restrict__ bq, const float* __restrict__ bk,
                const float* __restrict__ bv,
                float* __restrict__ yq, float* __restrict__ yk,
                float* __restrict__ yv)
{
    int sel = blockIdx.z >> 2, b = blockIdx.z & 3;
    const float* x; const float* w; const float* bia; float* y;
    if (sel == 0)      { x = q; w = wq; bia = bq; y = yq; }
    else if (sel == 1) { x = k; w = wk; bia = bk; y = yk; }
    else               { x = v; w = wv; bia = bv; y = yv; }
    conv_body(x, w, bia, y, b, blockIdx.y << 6, blockIdx.x << 7);
}

__global__ __launch_bounds__(256)
void conv1d_k(const float* __restrict__ x, const float* __restrict__ w,
              const float* __restrict__ bias, float* __restrict__ y)
{
    conv_body(x, w, bias, y, blockIdx.z, blockIdx.y << 6, blockIdx.x << 7);
}

// ---------------------------------------------------------------------------
// Flash attention (FFMA2 inner loops). Torch-faithful reshape:
//   A[b,h,n,d] = convout[b, n>>2, (n&3)*512 + h*64 + d]
// ---------------------------------------------------------------------------
__global__ __launch_bounds__(256)
void attn_k(const float* __restrict__ yq, const float* __restrict__ yk,
            const float* __restrict__ yv, float* __restrict__ z)
{
    __shared__ float QsT[64][64];  // [d][n ^ (d&60)]
    __shared__ float KP [64][64];  // K^T [d][j ^ (d&60)], then P [i][j]
    __shared__ float Vs [64][64];  // [j][d]

    const int tid = threadIdx.x;
    const int tx = tid & 15, ty = tid >> 4;
    const int b = blockIdx.z, h = blockIdx.y;
    const int t0 = blockIdx.x << 6;
    const size_t bbase = (size_t)b * (CH * LEN);
    const int hoff = h << 6;

    for (int idx = tid; idx < 1024; idx += 256) {
        int n = idx >> 4, ch = idx & 15, d = ch << 2;
        size_t off = bbase + (size_t)((t0 + n) >> 2) * LEN
                   + ((t0 + n) & 3) * 512 + hoff + d;
        float4 q4 = *(const float4*)(yq + off);
        int col = n ^ d;
        QsT[d + 0][col] = q4.x;
        QsT[d + 1][col] = q4.y;
        QsT[d + 2][col] = q4.z;
        QsT[d + 3][col] = q4.w;
    }

    float m[4], lsum[4];
    ull op[4][2];                  // O pairs over d-cols
    #pragma unroll
    for (int a = 0; a < 4; a++) {
        m[a] = -INFINITY; lsum[a] = 0.f;
        op[a][0] = 0ull; op[a][1] = 0ull;
    }

    for (int j0 = 0; j0 < LEN; j0 += 64) {
        __syncthreads();
        for (int idx = tid; idx < 1024; idx += 256) {
            int r = idx >> 4, ch = idx & 15;
            int n = j0 + r;
            size_t off = bbase + (size_t)(n >> 2) * LEN + (n & 3) * 512 + hoff + (ch << 2);
            float4 k4 = *(const float4*)(yk + off);
            int sw = r ^ (ch << 2);
            KP[(ch << 2) + 0][sw] = k4.x;
            KP[(ch << 2) + 1][sw] = k4.y;
            KP[(ch << 2) + 2][sw] = k4.z;
            KP[(ch << 2) + 3][sw] = k4.w;
            *(float4*)&Vs[r][ch << 2] = *(const float4*)(yv + off);
        }
        __syncthreads();

        // S = Q @ K^T : per d: 2 LDS.128 + 4 dup + 2 pack + 8 FFMA2 (32 MACs)
        ull sp[4][2];
        #pragma unroll
        for (int a = 0; a < 4; a++) { sp[a][0] = 0ull; sp[a][1] = 0ull; }
        #pragma unroll 16
        for (int d = 0; d < 64; d++) {
            const int dm = d & 60;
            float4 q4 = *(const float4*)&QsT[d][(ty << 2) ^ dm];
            float4 k4 = *(const float4*)&KP [d][(tx << 2) ^ dm];
            ull kp0 = f2_pack(k4.x, k4.y);
            ull kp1 = f2_pack(k4.z, k4.w);
            ull qd0 = f2_dup(q4.x), qd1 = f2_dup(q4.y);
            ull qd2 = f2_dup(q4.z), qd3 = f2_dup(q4.w);
            f2_fma(sp[0][0], qd0, kp0); f2_fma(sp[0][1], qd0, kp1);
            f2_fma(sp[1][0], qd1, kp0); f2_fma(sp[1][1], qd1, kp1);
            f2_fma(sp[2][0], qd2, kp0); f2_fma(sp[2][1], qd2, kp1);
            f2_fma(sp[3][0], qd3, kp0); f2_fma(sp[3][1], qd3, kp1);
        }
        __syncthreads();   // done reading KP; becomes P

        #pragma unroll
        for (int a = 0; a < 4; a++) {
            const float scale = 1.f / 64.f;
            float2 u0 = f2_unpack(sp[a][0]);
            float2 u1 = f2_unpack(sp[a][1]);
            float s0 = u0.x * scale, s1 = u0.y * scale;
            float s2 = u1.x * scale, s3 = u1.y * scale;
            float mx = fmaxf(fmaxf(s0, s1), fmaxf(s2, s3));
            mx = fmaxf(mx, __shfl_xor_sync(0xffffffffu, mx, 8));
            mx = fmaxf(mx, __shfl_xor_sync(0xffffffffu, mx, 4));
            mx = fmaxf(mx, __shfl_xor_sync(0xffffffffu, mx, 2));
            mx = fmaxf(mx, __shfl_xor_sync(0xffffffffu, mx, 1));
            float newm = fmaxf(m[a], mx);
            float corr = __expf(m[a] - newm);
            float p0 = __expf(s0 - newm);
            float p1 = __expf(s1 - newm);
            float p2 = __expf(s2 - newm);
            float p3 = __expf(s3 - newm);
            float rs = (p0 + p1) + (p2 + p3);
            rs += __shfl_xor_sync(0xffffffffu, rs, 8);
            rs += __shfl_xor_sync(0xffffffffu, rs, 4);
            rs += __shfl_xor_sync(0xffffffffu, rs, 2);
            rs += __shfl_xor_sync(0xffffffffu, rs, 1);
            lsum[a] = lsum[a] * corr + rs;
            m[a] = newm;
            ull cd = f2_dup(corr);
            f2_mul(op[a][0], cd);
            f2_mul(op[a][1], cd);
            *(float4*)&KP[(ty << 2) + a][tx << 2] = make_float4(p0, p1, p2, p3);
        }
        __syncthreads();

        // O += P @ V : per j: 4 scalar LDS + 1 LDS.128 + movs + 8 FFMA2
        #pragma unroll 8
        for (int j = 0; j < 64; j++) {
            float4 v4 = *(const float4*)&Vs[j][tx << 2];
            ull vp0 = f2_pack(v4.x, v4.y);
            ull vp1 = f2_pack(v4.z, v4.w);
            #pragma unroll
            for (int a = 0; a < 4; a++) {
                ull pd = f2_dup(KP[(ty << 2) + a][j]);
                f2_fma(op[a][0], pd, vp0);
                f2_fma(op[a][1], pd, vp1);
            }
        }
    }

    #pragma unroll
    for (int a = 0; a < 4; a++) {
        float inv = 1.f / lsum[a];
        int n = t0 + (ty << 2) + a;
        size_t off = bbase + (size_t)(n >> 2) * LEN + (n & 3) * 512 + hoff + (tx << 2);
        float2 u0 = f2_unpack(op[a][0]);
        float2 u1 = f2_unpack(op[a][1]);
        *(float4*)(z + off) = make_float4(u0.x * inv, u0.y * inv,
                                          u1.x * inv, u1.y * inv);
    }
}

// ---------------------------------------------------------------------------
extern "C" void kernel_launch(void* const* d_in, const int* in_sizes, int n_in,
                              void* d_out, int out_size)
{
    const float* q    = (const float*)d_in[0];
    const float* k    = (const float*)d_in[1];
    const float* v    = (const float*)d_in[2];
    const float* wq_w = (const float*)d_in[3];
    const float* wq_b = (const float*)d_in[4];
    const float* wk_w = (const float*)d_in[5];
    const float* wk_b = (const float*)d_in[6];
    const float* wv_w = (const float*)d_in[7];
    const float* wv_b = (const float*)d_in[8];
    const float* fc_w = (const float*)d_in[9];
    const float* fc_b = (const float*)d_in[10];
    float* out = (float*)d_out;

    float *yq, *yk, *yv, *zb;
    cudaGetSymbolAddress((void**)&yq, g_yq);
    cudaGetSymbolAddress((void**)&yk, g_yk);
    cudaGetSymbolAddress((void**)&yv, g_yv);
    cudaGetSymbolAddress((void**)&zb, g_z);

    dim3 blk(256);
    dim3 gqkv(LEN / 128, CH / 64, 3 * BATCH);   // (16, 8, 12)
    conv_qkv_k<<<gqkv, blk>>>(q, k, v, wq_w, wk_w, wv_w, wq_b, wk_b, wv_b,
                              yq, yk, yv);

    dim3 agrid(LEN / 64, 8, BATCH);             // (32, 8, 4)
    attn_k<<<agrid, blk>>>(yq, yk, yv, zb);

    dim3 gfc(LEN / 128, CH / 64, BATCH);        // (16, 8, 4)
    conv1d_k<<<gfc, blk>>>(zb, fc_w, fc_b, out);
}

// round 4
// speedup vs baseline: 1.1404x; 1.1404x over previous
#include <cuda_runtime.h>
#include <math.h>
#include <stdint.h>

#define BATCH 4
#define CH    512
#define LEN   2048

__device__ float g_yq[BATCH*CH*LEN];
__device__ float g_yk[BATCH*CH*LEN];
__device__ float g_yv[BATCH*CH*LEN];
__device__ float g_z [BATCH*CH*LEN];

// ---- tf32 helpers: 3xTF32 split (fp32-equivalent accuracy) -----------------
__device__ __forceinline__ uint32_t tf32_rna(float a) {
    uint32_t r; asm("cvt.rna.tf32.f32 %0, %1;" : "=r"(r) : "f"(a)); return r;
}
__device__ __forceinline__ void split_tf32(float a, uint32_t& hi, uint32_t& lo) {
    hi = tf32_rna(a);
    lo = tf32_rna(a - __uint_as_float(hi));
}
__device__ __forceinline__ void mma_tf32(float4& d, const uint32_t* a,
                                         uint32_t b0, uint32_t b1) {
    asm volatile(
        "mma.sync.aligned.m16n8k8.row.col.f32.tf32.tf32.f32 "
        "{%0,%1,%2,%3},{%4,%5,%6,%7},{%8,%9},{%0,%1,%2,%3};"
        : "+f"(d.x), "+f"(d.y), "+f"(d.z), "+f"(d.w)
        : "r"(a[0]), "r"(a[1]), "r"(a[2]), "r"(a[3]), "r"(b0), "r"(b1));
}

// ---------------------------------------------------------------------------
// Conv1d (k=3, 'same') on tensor cores. Per tap t: Y += W_t[co][ci] X[ci][pos+t-1].
// Block tile 64co x 128pos, 256 threads = 8 warps, warp tile 16co x 64pos.
// K staged 8 ci at a time: Xs[8][130] window, Ws[24][64] (rows = ci*3+t).
// Pitches 72 / 136 give conflict-free fragment gathers (bank = g + {0,8,16,24}).
// ---------------------------------------------------------------------------
#define WS_PITCH 72
#define XS_PITCH 136

__device__ __forceinline__
void conv_body(const float* __restrict__ x, const float* __restrict__ w,
               const float* __restrict__ bias, float* __restrict__ y,
               int b, int co0, int l0)
{
    __shared__ float Ws[24][WS_PITCH];
    __shared__ float Xs[8][XS_PITCH];

    const int tid  = threadIdx.x;
    const int lane = tid & 31;
    const int wid  = tid >> 5;
    const int g    = lane >> 2;      // group id 0..7
    const int tg   = lane & 3;       // thread-in-group 0..3
    const int wco  = (wid & 3) << 4; // warp co offset: 0,16,32,48
    const int wpos = (wid >> 2) << 6;// warp pos offset: 0,64
    const float* xb = x + (size_t)b * (CH * LEN);

    float4 acc[8];
    #pragma unroll
    for (int i = 0; i < 8; i++) acc[i] = make_float4(0.f, 0.f, 0.f, 0.f);

    const int xr  = tid >> 5;        // X stage row 0..7
    const int xc0 = tid & 31;

    for (int ci0 = 0; ci0 < CH; ci0 += 8) {
        __syncthreads();
        // Stage X: 8 ci rows, cols 0..129  <->  global pos l0-1 .. l0+128
        {
            const float* xrow = xb + (size_t)(ci0 + xr) * LEN + (l0 - 1);
            for (int c = xc0; c < 130; c += 32) {
                int gl = l0 - 1 + c;
                Xs[xr][c] = (gl >= 0 && gl < LEN) ? xrow[c] : 0.f;
            }
        }
        // Stage W: rows r = ci_local*3 + t (0..23), 64 co. Global w[co][ci][t]
        // is contiguous in r -> float4 loads.
        for (int i = tid; i < 64 * 6; i += 256) {
            int co = i / 6, qq = i - co * 6;
            float4 w4 = *(const float4*)(w + (size_t)(co0 + co) * (CH * 3)
                                           + ci0 * 3 + (qq << 2));
            int r = qq << 2;
            Ws[r + 0][co] = w4.x; Ws[r + 1][co] = w4.y;
            Ws[r + 2][co] = w4.z; Ws[r + 3][co] = w4.w;
        }
        __syncthreads();

        #pragma unroll
        for (int t = 0; t < 3; t++) {
            // A fragment (m16k8, row-major): rows g/g+8, k = tg / tg+4
            uint32_t ahi[4], alo[4];
            const int r0 = tg * 3 + t;
            split_tf32(Ws[r0     ][wco + g    ], ahi[0], alo[0]);
            split_tf32(Ws[r0     ][wco + g + 8], ahi[1], alo[1]);
            split_tf32(Ws[r0 + 12][wco + g    ], ahi[2], alo[2]);
            split_tf32(Ws[r0 + 12][wco + g + 8], ahi[3], alo[3]);
            #pragma unroll
            for (int a2 = 0; a2 < 8; a2++) {
                // B fragment (k8n8, col-major): k = tg/tg+4, n = g
                const int c = wpos + (a2 << 3) + g + t;
                uint32_t bh0, bl0, bh1, bl1;
                split_tf32(Xs[tg    ][c], bh0, bl0);
                split_tf32(Xs[tg + 4][c], bh1, bl1);
                mma_tf32(acc[a2], ahi, bh0, bh1);
                mma_tf32(acc[a2], alo, bh0, bh1);
                mma_tf32(acc[a2], ahi, bl0, bl1);
            }
        }
    }

    // Epilogue: C layout rows g/g+8, cols 2*tg, 2*tg+1 per n-atom
    const int row = co0 + wco + g;
    const float bv0 = bias[row], bv1 = bias[row + 8];
    float* y0 = y + ((size_t)b * CH + row) * LEN + l0 + wpos + (tg << 1);
    #pragma unroll
    for (int a2 = 0; a2 < 8; a2++) {
        *(float2*)(y0 + (a2 << 3)) =
            make_float2(acc[a2].x + bv0, acc[a2].y + bv0);
        *(float2*)(y0 + (size_t)8 * LEN + (a2 << 3)) =
            make_float2(acc[a2].z + bv1, acc[a2].w + bv1);
    }
}

__global__ __launch_bounds__(256)
void conv_qkv_k(const float* __restrict__ q, const float* __restrict__ k,
                const float* __restrict__ v,
                const float* __restrict__ wq, const float* __restrict__ wk,
                const float* __restrict__ wv,
                const float* __restrict__ bq, const float* __restrict__ bk,
                const float* __restrict__ bv,
                float* __restrict__ yq, float* __restrict__ yk,
                float* __restrict__ yv)
{
    int sel = blockIdx.z >> 2, b = blockIdx.z & 3;
    const float* x; const float* w; const float* bia; float* y;
    if (sel == 0)      { x = q; w = wq; bia = bq; y = yq; }
    else if (sel == 1) { x = k; w = wk; bia = bk; y = yk; }
    else               { x = v; w = wv; bia = bv; y = yv; }
    conv_body(x, w, bia, y, b, blockIdx.y << 6, blockIdx.x << 7);
}

__global__ __launch_bounds__(256)
void conv1d_k(const float* __restrict__ x, const float* __restrict__ w,
              const float* __restrict__ bias, float* __restrict__ y)
{
    conv_body(x, w, bias, y, blockIdx.z, blockIdx.y << 6, blockIdx.x << 7);
}

// ---------------------------------------------------------------------------
// Flash attention (best measured variant, R2). Torch-faithful reshape:
//   A[b,h,n,d] = convout[b, n>>2, (n&3)*512 + h*64 + d]
// ---------------------------------------------------------------------------
__global__ __launch_bounds__(256)
void attn_k(const float* __restrict__ yq, const float* __restrict__ yk,
            const float* __restrict__ yv, float* __restrict__ z)
{
    __shared__ float QsT[64][64];  // [d][n ^ (d&60)]
    __shared__ float KP [64][64];  // K^T [d][j ^ (d&60)], then P [i][j]
    __shared__ float Vs [64][64];  // [j][d]

    const int tid = threadIdx.x;
    const int tx = tid & 15, ty = tid >> 4;
    const int b = blockIdx.z, h = blockIdx.y;
    const int t0 = blockIdx.x << 6;
    const size_t bbase = (size_t)b * (CH * LEN);
    const int hoff = h << 6;

    for (int idx = tid; idx < 1024; idx += 256) {
        int n = idx >> 4, ch = idx & 15, d = ch << 2;
        size_t off = bbase + (size_t)((t0 + n) >> 2) * LEN
                   + ((t0 + n) & 3) * 512 + hoff + d;
        float4 q4 = *(const float4*)(yq + off);
        int col = n ^ d;
        QsT[d + 0][col] = q4.x;
        QsT[d + 1][col] = q4.y;
        QsT[d + 2][col] = q4.z;
        QsT[d + 3][col] = q4.w;
    }

    float m[4], lsum[4], o[4][4];
    #pragma unroll
    for (int a = 0; a < 4; a++) {
        m[a] = -INFINITY; lsum[a] = 0.f;
        #pragma unroll
        for (int c = 0; c < 4; c++) o[a][c] = 0.f;
    }

    for (int j0 = 0; j0 < LEN; j0 += 64) {
        __syncthreads();
        for (int idx = tid; idx < 1024; idx += 256) {
            int r = idx >> 4, ch = idx & 15;
            int n = j0 + r;
            size_t off = bbase + (size_t)(n >> 2) * LEN + (n & 3) * 512 + hoff + (ch << 2);
            float4 k4 = *(const float4*)(yk + off);
            int sw = r ^ (ch << 2);
            KP[(ch << 2) + 0][sw] = k4.x;
            KP[(ch << 2) + 1][sw] = k4.y;
            KP[(ch << 2) + 2][sw] = k4.z;
            KP[(ch << 2) + 3][sw] = k4.w;
            *(float4*)&Vs[r][ch << 2] = *(const float4*)(yv + off);
        }
        __syncthreads();

        float s[4][4] = {};
        #pragma unroll 16
        for (int d = 0; d < 64; d++) {
            const int dm = d & 60;
            float4 q4 = *(const float4*)&QsT[d][(ty << 2) ^ dm];
            float4 k4 = *(const float4*)&KP [d][(tx << 2) ^ dm];
            float qv[4] = {q4.x, q4.y, q4.z, q4.w};
            float kv[4] = {k4.x, k4.y, k4.z, k4.w};
            #pragma unroll
            for (int a = 0; a < 4; a++)
                #pragma unroll
                for (int c = 0; c < 4; c++)
                    s[a][c] = fmaf(qv[a], kv[c], s[a][c]);
        }
        __syncthreads();

        #pragma unroll
        for (int a = 0; a < 4; a++) {
            const float scale = 1.f / 64.f;
            float s0 = s[a][0] * scale, s1 = s[a][1] * scale;
            float s2 = s[a][2] * scale, s3 = s[a][3] * scale;
            float mx = fmaxf(fmaxf(s0, s1), fmaxf(s2, s3));
            mx = fmaxf(mx, __shfl_xor_sync(0xffffffffu, mx, 8));
            mx = fmaxf(mx, __shfl_xor_sync(0xffffffffu, mx, 4));
            mx = fmaxf(mx, __shfl_xor_sync(0xffffffffu, mx, 2));
            mx = fmaxf(mx, __shfl_xor_sync(0xffffffffu, mx, 1));
            float newm = fmaxf(m[a], mx);
            float corr = __expf(m[a] - newm);
            float p0 = __expf(s0 - newm);
            float p1 = __expf(s1 - newm);
            float p2 = __expf(s2 - newm);
            float p3 = __expf(s3 - newm);
            float rs = (p0 + p1) + (p2 + p3);
            rs += __shfl_xor_sync(0xffffffffu, rs, 8);
            rs += __shfl_xor_sync(0xffffffffu, rs, 4);
            rs += __shfl_xor_sync(0xffffffffu, rs, 2);
            rs += __shfl_xor_sync(0xffffffffu, rs, 1);
            lsum[a] = lsum[a] * corr + rs;
            m[a] = newm;
            o[a][0] *= corr; o[a][1] *= corr; o[a][2] *= corr; o[a][3] *= corr;
            *(float4*)&KP[(ty << 2) + a][tx << 2] = make_float4(p0, p1, p2, p3);
        }
        __syncthreads();

        #pragma unroll 8
        for (int j = 0; j < 64; j++) {
            float pv[4];
            #pragma unroll
            for (int a = 0; a < 4; a++) pv[a] = KP[(ty << 2) + a][j];
            float4 v4 = *(const float4*)&Vs[j][tx << 2];
            float vv[4] = {v4.x, v4.y, v4.z, v4.w};
            #pragma unroll
            for (int a = 0; a < 4; a++)
                #pragma unroll
                for (int c = 0; c < 4; c++)
                    o[a][c] = fmaf(pv[a], vv[c], o[a][c]);
        }
    }

    #pragma unroll
    for (int a = 0; a < 4; a++) {
        float inv = 1.f / lsum[a];
        int n = t0 + (ty << 2) + a;
        size_t off = bbase + (size_t)(n >> 2) * LEN + (n & 3) * 512 + hoff + (tx << 2);
        *(float4*)(z + off) = make_float4(o[a][0] * inv, o[a][1] * inv,
                                          o[a][2] * inv, o[a][3] * inv);
    }
}

// ---------------------------------------------------------------------------
extern "C" void kernel_launch(void* const* d_in, const int* in_sizes, int n_in,
                              void* d_out, int out_size)
{
    const float* q    = (const float*)d_in[0];
    const float* k    = (const float*)d_in[1];
    const float* v    = (const float*)d_in[2];
    const float* wq_w = (const float*)d_in[3];
    const float* wq_b = (const float*)d_in[4];
    const float* wk_w = (const float*)d_in[5];
    const float* wk_b = (const float*)d_in[6];
    const float* wv_w = (const float*)d_in[7];
    const float* wv_b = (const float*)d_in[8];
    const float* fc_w = (const float*)d_in[9];
    const float* fc_b = (const float*)d_in[10];
    float* out = (float*)d_out;

    float *yq, *yk, *yv, *zb;
    cudaGetSymbolAddress((void**)&yq, g_yq);
    cudaGetSymbolAddress((void**)&yk, g_yk);
    cudaGetSymbolAddress((void**)&yv, g_yv);
    cudaGetSymbolAddress((void**)&zb, g_z);

    dim3 blk(256);
    dim3 gqkv(LEN / 128, CH / 64, 3 * BATCH);   // (16, 8, 12)
    conv_qkv_k<<<gqkv, blk>>>(q, k, v, wq_w, wk_w, wv_w, wq_b, wk_b, wv_b,
                              yq, yk, yv);

    dim3 agrid(LEN / 64, 8, BATCH);             // (32, 8, 4)
    attn_k<<<agrid, blk>>>(yq, yk, yv, zb);

    dim3 gfc(LEN / 128, CH / 64, BATCH);        // (16, 8, 4)
    conv1d_k<<<gfc, blk>>>(zb, fc_w, fc_b, out);
}

// round 5
// speedup vs baseline: 1.6917x; 1.4835x over previous
#include <cuda_runtime.h>
#include <math.h>
#include <stdint.h>

#define BATCH 4
#define CH    512
#define LEN   2048

__device__ float g_yq[BATCH*CH*LEN];
__device__ float g_yk[BATCH*CH*LEN];
__device__ float g_yv[BATCH*CH*LEN];
__device__ float g_z [BATCH*CH*LEN];

// ---- tf32 helpers -----------------------------------------------------------
__device__ __forceinline__ uint32_t tf32_rna(float a) {
    uint32_t r; asm("cvt.rna.tf32.f32 %0, %1;" : "=r"(r) : "f"(a)); return r;
}
__device__ __forceinline__ void split_tf32(float a, uint32_t& hi, uint32_t& lo) {
    hi = tf32_rna(a);
    lo = tf32_rna(a - __uint_as_float(hi));
}
__device__ __forceinline__ void mma_tf32(float4& d, const uint32_t* a,
                                         uint32_t b0, uint32_t b1) {
    asm volatile(
        "mma.sync.aligned.m16n8k8.row.col.f32.tf32.tf32.f32 "
        "{%0,%1,%2,%3},{%4,%5,%6,%7},{%8,%9},{%0,%1,%2,%3};"
        : "+f"(d.x), "+f"(d.y), "+f"(d.z), "+f"(d.w)
        : "r"(a[0]), "r"(a[1]), "r"(a[2]), "r"(a[3]), "r"(b0), "r"(b1));
}

// ---------------------------------------------------------------------------
// Conv1d (k=3, 'same') on tensor cores, 3xTF32, splits hoisted to staging.
// Block tile 64co x 128pos, 256 threads = 8 warps, warp tile 16co x 64pos.
// ---------------------------------------------------------------------------
#define WS_PITCH 72    // 72 % 32 == 8 -> A-frag reads conflict-free
#define XS_PITCH 136   // 136 % 32 == 8 -> B-frag reads conflict-free

__device__ __forceinline__
void conv_body(const float* __restrict__ x, const float* __restrict__ w,
               const float* __restrict__ bias, float* __restrict__ y,
               int b, int co0, int l0)
{
    __shared__ uint32_t Wh[24][WS_PITCH], Wl[24][WS_PITCH];
    __shared__ uint32_t Xh[8][XS_PITCH],  Xl[8][XS_PITCH];

    const int tid  = threadIdx.x;
    const int lane = tid & 31;
    const int wid  = tid >> 5;
    const int g    = lane >> 2;       // 0..7
    const int tg   = lane & 3;        // 0..3
    const int wco  = (wid & 3) << 4;  // 0,16,32,48
    const int wpos = (wid >> 2) << 6; // 0,64
    const float* xb = x + (size_t)b * (CH * LEN);

    float4 acc[8];
    #pragma unroll
    for (int i = 0; i < 8; i++) acc[i] = make_float4(0.f, 0.f, 0.f, 0.f);

    const int xr  = tid >> 5;
    const int xc0 = tid & 31;

    for (int ci0 = 0; ci0 < CH; ci0 += 8) {
        __syncthreads();
        {   // Stage X rows (pre-split): cols 0..129 <-> pos l0-1 .. l0+128
            const float* xrow = xb + (size_t)(ci0 + xr) * LEN + (l0 - 1);
            for (int c = xc0; c < 130; c += 32) {
                int gl = l0 - 1 + c;
                float v = (gl >= 0 && gl < LEN) ? xrow[c] : 0.f;
                uint32_t hi, lo; split_tf32(v, hi, lo);
                Xh[xr][c] = hi; Xl[xr][c] = lo;
            }
        }
        // Stage W (pre-split): rows r = ci_local*3 + t
        for (int i = tid; i < 64 * 6; i += 256) {
            int co = i / 6, qq = i - co * 6;
            float4 w4 = *(const float4*)(w + (size_t)(co0 + co) * (CH * 3)
                                           + ci0 * 3 + (qq << 2));
            int r = qq << 2;
            uint32_t hi, lo;
            split_tf32(w4.x, hi, lo); Wh[r+0][co] = hi; Wl[r+0][co] = lo;
            split_tf32(w4.y, hi, lo); Wh[r+1][co] = hi; Wl[r+1][co] = lo;
            split_tf32(w4.z, hi, lo); Wh[r+2][co] = hi; Wl[r+2][co] = lo;
            split_tf32(w4.w, hi, lo); Wh[r+3][co] = hi; Wl[r+3][co] = lo;
        }
        __syncthreads();

        #pragma unroll
        for (int t = 0; t < 3; t++) {
            uint32_t ah[4], al[4];
            const int r0 = tg * 3 + t;
            ah[0] = Wh[r0     ][wco + g    ]; al[0] = Wl[r0     ][wco + g    ];
            ah[1] = Wh[r0     ][wco + g + 8]; al[1] = Wl[r0     ][wco + g + 8];
            ah[2] = Wh[r0 + 12][wco + g    ]; al[2] = Wl[r0 + 12][wco + g    ];
            ah[3] = Wh[r0 + 12][wco + g + 8]; al[3] = Wl[r0 + 12][wco + g + 8];
            #pragma unroll
            for (int a2 = 0; a2 < 8; a2++) {
                const int c = wpos + (a2 << 3) + g + t;
                uint32_t bh0 = Xh[tg    ][c];
                uint32_t bh1 = Xh[tg + 4][c];
                uint32_t bl0 = Xl[tg    ][c];
                uint32_t bl1 = Xl[tg + 4][c];
                mma_tf32(acc[a2], ah, bh0, bh1);
                mma_tf32(acc[a2], al, bh0, bh1);
                mma_tf32(acc[a2], ah, bl0, bl1);
            }
        }
    }

    const int row = co0 + wco + g;
    const float bv0 = bias[row], bv1 = bias[row + 8];
    float* y0 = y + ((size_t)b * CH + row) * LEN + l0 + wpos + (tg << 1);
    #pragma unroll
    for (int a2 = 0; a2 < 8; a2++) {
        *(float2*)(y0 + (a2 << 3)) =
            make_float2(acc[a2].x + bv0, acc[a2].y + bv0);
        *(float2*)(y0 + (size_t)8 * LEN + (a2 << 3)) =
            make_float2(acc[a2].z + bv1, acc[a2].w + bv1);
    }
}

__global__ __launch_bounds__(256)
void conv_qkv_k(const float* __restrict__ q, const float* __restrict__ k,
                const float* __restrict__ v,
                const float* __restrict__ wq, const float* __restrict__ wk,
                const float* __restrict__ wv,
                const float* __restrict__ bq, const float* __restrict__ bk,
                const float* __restrict__ bv,
                float* __restrict__ yq, float* __restrict__ yk,
                float* __restrict__ yv)
{
    int sel = blockIdx.z >> 2, b = blockIdx.z & 3;
    const float* x; const float* w; const float* bia; float* y;
    if (sel == 0)      { x = q; w = wq; bia = bq; y = yq; }
    else if (sel == 1) { x = k; w = wk; bia = bk; y = yk; }
    else               { x = v; w = wv; bia = bv; y = yv; }
    conv_body(x, w, bia, y, b, blockIdx.y << 6, blockIdx.x << 7);
}

__global__ __launch_bounds__(256)
void conv1d_k(const float* __restrict__ x, const float* __restrict__ w,
              const float* __restrict__ bias, float* __restrict__ y)
{
    conv_body(x, w, bias, y, blockIdx.z, blockIdx.y << 6, blockIdx.x << 7);
}

// ---------------------------------------------------------------------------
// Flash attention on tensor cores (single-pass tf32; error << 1e-3 budget).
// Block = (64-query tile, h, b); 128 threads = 4 warps; warp owns 16 rows.
// Torch-faithful reshape: A[b,h,n,d] = conv[b, n>>2, (n&3)*512 + h*64 + d].
// KP pitch 68 (==4 mod 32) and Vs pitch 72 (==8 mod 32): fragment reads
// conflict-free. K region is reused for P after an intra-loop sync.
// ---------------------------------------------------------------------------
#define KP_PITCH 68
#define V_PITCH  72

__global__ __launch_bounds__(128)
void attn_k(const float* __restrict__ yq, const float* __restrict__ yk,
            const float* __restrict__ yv, float* __restrict__ z)
{
    __shared__ uint32_t KP[64 * KP_PITCH];  // K tf32 [j][d] -> P tf32 [row][j]
    __shared__ uint32_t Vs[64 * V_PITCH];   // V tf32 [j][d]

    const int tid  = threadIdx.x;
    const int lane = tid & 31;
    const int wid  = tid >> 5;     // 0..3
    const int g    = lane >> 2;    // 0..7
    const int tg   = lane & 3;     // 0..3
    const int m0   = wid << 4;     // warp's first query row

    const int b = blockIdx.z, h = blockIdx.y;
    const int t0 = blockIdx.x << 6;
    const size_t bbase = (size_t)b * (CH * LEN);
    const int hoff = h << 6;

#define AOFF(n) (bbase + (size_t)((n) >> 2) * LEN + ((n) & 3) * 512 + hoff)

    // Q fragments in registers (rows m0+g, m0+g+8), tf32 single-pass
    uint32_t qa[8][4];
    {
        const float* q0 = yq + AOFF(t0 + m0 + g);
        const float* q1 = yq + AOFF(t0 + m0 + g + 8);
        #pragma unroll
        for (int kt = 0; kt < 8; kt++) {
            qa[kt][0] = tf32_rna(q0[tg + 8 * kt]);
            qa[kt][1] = tf32_rna(q1[tg + 8 * kt]);
            qa[kt][2] = tf32_rna(q0[tg + 4 + 8 * kt]);
            qa[kt][3] = tf32_rna(q1[tg + 4 + 8 * kt]);
        }
    }

    float mrow[2] = {-INFINITY, -INFINITY};
    float lrow[2] = {0.f, 0.f};
    float4 o[8];
    #pragma unroll
    for (int nt = 0; nt < 8; nt++) o[nt] = make_float4(0.f, 0.f, 0.f, 0.f);

    for (int j0 = 0; j0 < LEN; j0 += 64) {
        __syncthreads();   // everyone done with prev P (in KP) and Vs
        // Stage K,V tiles as tf32
        for (int i = tid; i < 1024; i += 128) {       // float4 units
            int r = i >> 4, c4 = (i & 15) << 2;
            size_t off = AOFF(j0 + r) + c4;
            float4 kk = *(const float4*)(yk + off);
            float4 vv = *(const float4*)(yv + off);
            uint4 ku = make_uint4(tf32_rna(kk.x), tf32_rna(kk.y),
                                  tf32_rna(kk.z), tf32_rna(kk.w));
            uint4 vu = make_uint4(tf32_rna(vv.x), tf32_rna(vv.y),
                                  tf32_rna(vv.z), tf32_rna(vv.w));
            *(uint4*)&KP[r * KP_PITCH + c4] = ku;
            *(uint4*)&Vs[r * V_PITCH  + c4] = vu;
        }
        __syncthreads();

        // S = Q @ K^T  (warp computes 16 x 64)
        float4 sA[8];
        #pragma unroll
        for (int nt = 0; nt < 8; nt++) sA[nt] = make_float4(0.f, 0.f, 0.f, 0.f);
        #pragma unroll
        for (int kt = 0; kt < 8; kt++) {
            #pragma unroll
            for (int nt = 0; nt < 8; nt++) {
                uint32_t b0 = KP[(nt * 8 + g) * KP_PITCH + tg + 8 * kt];
                uint32_t b1 = KP[(nt * 8 + g) * KP_PITCH + tg + 4 + 8 * kt];
                mma_tf32(sA[nt], qa[kt], b0, b1);
            }
        }
        __syncthreads();   // all warps done reading K; region becomes P

        // Online softmax on rows r0 = m0+g (x,y) and r1 = m0+g+8 (z,w)
        const float scale = 1.f / 64.f;
        float mx0 = -INFINITY, mx1 = -INFINITY;
        #pragma unroll
        for (int nt = 0; nt < 8; nt++) {
            mx0 = fmaxf(mx0, fmaxf(sA[nt].x, sA[nt].y));
            mx1 = fmaxf(mx1, fmaxf(sA[nt].z, sA[nt].w));
        }
        mx0 *= scale; mx1 *= scale;
        mx0 = fmaxf(mx0, __shfl_xor_sync(0xffffffffu, mx0, 1));
        mx0 = fmaxf(mx0, __shfl_xor_sync(0xffffffffu, mx0, 2));
        mx1 = fmaxf(mx1, __shfl_xor_sync(0xffffffffu, mx1, 1));
        mx1 = fmaxf(mx1, __shfl_xor_sync(0xffffffffu, mx1, 2));
        float nm0 = fmaxf(mrow[0], mx0);
        float nm1 = fmaxf(mrow[1], mx1);
        float corr0 = __expf(mrow[0] - nm0);
        float corr1 = __expf(mrow[1] - nm1);
        mrow[0] = nm0; mrow[1] = nm1;

        float rs0 = 0.f, rs1 = 0.f;
        uint32_t* Prow0 = &KP[(m0 + g)     * KP_PITCH + (tg << 1)];
        uint32_t* Prow1 = &KP[(m0 + g + 8) * KP_PITCH + (tg << 1)];
        #pragma unroll
        for (int nt = 0; nt < 8; nt++) {
            float p00 = __expf(sA[nt].x * scale - nm0);
            float p01 = __expf(sA[nt].y * scale - nm0);
            float p10 = __expf(sA[nt].z * scale - nm1);
            float p11 = __expf(sA[nt].w * scale - nm1);
            rs0 += p00 + p01;
            rs1 += p10 + p11;
            Prow0[nt * 8 + 0] = tf32_rna(p00);
            Prow0[nt * 8 + 1] = tf32_rna(p01);
            Prow1[nt * 8 + 0] = tf32_rna(p10);
            Prow1[nt * 8 + 1] = tf32_rna(p11);
            o[nt].x *= corr0; o[nt].y *= corr0;
            o[nt].z *= corr1; o[nt].w *= corr1;
        }
        rs0 += __shfl_xor_sync(0xffffffffu, rs0, 1);
        rs0 += __shfl_xor_sync(0xffffffffu, rs0, 2);
        rs1 += __shfl_xor_sync(0xffffffffu, rs1, 1);
        rs1 += __shfl_xor_sync(0xffffffffu, rs1, 2);
        lrow[0] = lrow[0] * corr0 + rs0;
        lrow[1] = lrow[1] * corr1 + rs1;
        __syncwarp();      // warp-private P rows visible

        // O += P @ V  (A = P rows m0..m0+16, B = V col-major)
        #pragma unroll
        for (int kt = 0; kt < 8; kt++) {
            uint32_t pa[4];
            pa[0] = KP[(m0 + g)     * KP_PITCH + tg + 8 * kt];
            pa[1] = KP[(m0 + g + 8) * KP_PITCH + tg + 8 * kt];
            pa[2] = KP[(m0 + g)     * KP_PITCH + tg + 4 + 8 * kt];
            pa[3] = KP[(m0 + g + 8) * KP_PITCH + tg + 4 + 8 * kt];
            #pragma unroll
            for (int nt = 0; nt < 8; nt++) {
                uint32_t b0 = Vs[(tg + 8 * kt)     * V_PITCH + nt * 8 + g];
                uint32_t b1 = Vs[(tg + 4 + 8 * kt) * V_PITCH + nt * 8 + g];
                mma_tf32(o[nt], pa, b0, b1);
            }
        }
    }

    // Epilogue: rows n0 = t0+m0+g, n1 = n0+8; cols d = 8*nt + 2*tg (+1)
    const float inv0 = 1.f / lrow[0];
    const float inv1 = 1.f / lrow[1];
    float* z0 = z + AOFF(t0 + m0 + g)     + (tg << 1);
    float* z1 = z + AOFF(t0 + m0 + g + 8) + (tg << 1);
    #pragma unroll
    for (int nt = 0; nt < 8; nt++) {
        *(float2*)(z0 + nt * 8) = make_float2(o[nt].x * inv0, o[nt].y * inv0);
        *(float2*)(z1 + nt * 8) = make_float2(o[nt].z * inv1, o[nt].w * inv1);
    }
#undef AOFF
}

// ---------------------------------------------------------------------------
extern "C" void kernel_launch(void* const* d_in, const int* in_sizes, int n_in,
                              void* d_out, int out_size)
{
    const float* q    = (const float*)d_in[0];
    const float* k    = (const float*)d_in[1];
    const float* v    = (const float*)d_in[2];
    const float* wq_w = (const float*)d_in[3];
    const float* wq_b = (const float*)d_in[4];
    const float* wk_w = (const float*)d_in[5];
    const float* wk_b = (const float*)d_in[6];
    const float* wv_w = (const float*)d_in[7];
    const float* wv_b = (const float*)d_in[8];
    const float* fc_w = (const float*)d_in[9];
    const float* fc_b = (const float*)d_in[10];
    float* out = (float*)d_out;

    float *yq, *yk, *yv, *zb;
    cudaGetSymbolAddress((void**)&yq, g_yq);
    cudaGetSymbolAddress((void**)&yk, g_yk);
    cudaGetSymbolAddress((void**)&yv, g_yv);
    cudaGetSymbolAddress((void**)&zb, g_z);

    dim3 gqkv(LEN / 128, CH / 64, 3 * BATCH);   // (16, 8, 12)
    conv_qkv_k<<<gqkv, 256>>>(q, k, v, wq_w, wk_w, wv_w, wq_b, wk_b, wv_b,
                              yq, yk, yv);

    dim3 agrid(LEN / 64, 8, BATCH);             // (32, 8, 4)
    attn_k<<<agrid, 128>>>(yq, yk, yv, zb);

    dim3 gfc(LEN / 128, CH / 64, BATCH);        // (16, 8, 4)
    conv1d_k<<<gfc, 256>>>(zb, fc_w, fc_b, out);
}

// round 6
// speedup vs baseline: 2.2318x; 1.3192x over previous
#include <cuda_runtime.h>
#include <math.h>
#include <stdint.h>

#define BATCH 4
#define CH    512
#define LEN   2048

__device__ float g_yq[BATCH*CH*LEN];
__device__ float g_yk[BATCH*CH*LEN];
__device__ float g_yv[BATCH*CH*LEN];
__device__ float g_z [BATCH*CH*LEN];

// ---- tf32 helpers -----------------------------------------------------------
__device__ __forceinline__ uint32_t tf32_rna(float a) {
    uint32_t r; asm("cvt.rna.tf32.f32 %0, %1;" : "=r"(r) : "f"(a)); return r;
}
__device__ __forceinline__ void split_tf32(float a, uint32_t& hi, uint32_t& lo) {
    hi = tf32_rna(a);
    lo = tf32_rna(a - __uint_as_float(hi));
}
__device__ __forceinline__ void mma_tf32(float4& d, const uint32_t* a,
                                         uint32_t b0, uint32_t b1) {
    asm volatile(
        "mma.sync.aligned.m16n8k8.row.col.f32.tf32.tf32.f32 "
        "{%0,%1,%2,%3},{%4,%5,%6,%7},{%8,%9},{%0,%1,%2,%3};"
        : "+f"(d.x), "+f"(d.y), "+f"(d.z), "+f"(d.w)
        : "r"(a[0]), "r"(a[1]), "r"(a[2]), "r"(a[3]), "r"(b0), "r"(b1));
}

// ---------------------------------------------------------------------------
// Conv1d (k=3, 'same') on tensor cores. W always split (hi/lo). X split only
// when SPLITX (fc conv, fp32-grade); QKV convs use single-pass tf32 X.
// Software-pipelined: next chunk prefetched into registers during compute.
// Block tile 64co x 128pos, 256 threads = 8 warps, warp tile 16co x 64pos.
// ---------------------------------------------------------------------------
#define WS_PITCH 72    // 72 % 32 == 8 -> A-frag reads conflict-free
#define XS_PITCH 136   // 136 % 32 == 8 -> B-frag reads conflict-free

template<bool SPLITX>
__device__ __forceinline__
void conv_body(const float* __restrict__ x, const float* __restrict__ w,
               const float* __restrict__ bias, float* __restrict__ y,
               int b, int co0, int l0)
{
    __shared__ uint32_t Wh[24][WS_PITCH], Wl[24][WS_PITCH];
    __shared__ uint32_t Xh[8][XS_PITCH];
    __shared__ uint32_t Xl[8][XS_PITCH];   // used only if SPLITX

    const int tid  = threadIdx.x;
    const int lane = tid & 31;
    const int wid  = tid >> 5;
    const int g    = lane >> 2;       // 0..7
    const int tg   = lane & 3;        // 0..3
    const int wco  = (wid & 3) << 4;  // 0,16,32,48
    const int wpos = (wid >> 2) << 6; // 0,64
    const float* xb = x + (size_t)b * (CH * LEN);

    float4 acc[8];
    #pragma unroll
    for (int i = 0; i < 8; i++) acc[i] = make_float4(0.f, 0.f, 0.f, 0.f);

    // staging roles
    const int xr     = tid >> 5;        // X row 0..7 (one row per warp, coalesced)
    const int wco_ld = tid >> 2;        // 0..63
    const int wr_ld  = (tid & 3) * 6;   // 0,6,12,18

    float rx[5], rw[6];

    // ---- prefetch chunk 0 ----
    {
        const float* xrow = xb + (size_t)xr * LEN + (l0 - 1);
        #pragma unroll
        for (int i = 0; i < 5; i++) {
            int c = lane + (i << 5);
            int gl = l0 - 1 + c;
            rx[i] = (c < 130 && gl >= 0 && gl < LEN) ? xrow[c] : 0.f;
        }
        const float* wp = w + (size_t)(co0 + wco_ld) * (CH * 3) + wr_ld;
        #pragma unroll
        for (int i = 0; i < 6; i++) rw[i] = wp[i];
    }

    for (int ci0 = 0; ci0 < CH; ci0 += 8) {
        // ---- store prefetched chunk to smem (with tf32 conversion) ----
        #pragma unroll
        for (int i = 0; i < 5; i++) {
            int c = lane + (i << 5);
            if (c < 130) {
                if (SPLITX) {
                    uint32_t hi, lo; split_tf32(rx[i], hi, lo);
                    Xh[xr][c] = hi; Xl[xr][c] = lo;
                } else {
                    Xh[xr][c] = tf32_rna(rx[i]);
                }
            }
        }
        #pragma unroll
        for (int i = 0; i < 6; i++) {
            uint32_t hi, lo; split_tf32(rw[i], hi, lo);
            Wh[wr_ld + i][wco_ld] = hi;
            Wl[wr_ld + i][wco_ld] = lo;
        }
        __syncthreads();

        // ---- prefetch next chunk into registers (overlaps with MMAs) ----
        if (ci0 + 8 < CH) {
            const float* xrow = xb + (size_t)(ci0 + 8 + xr) * LEN + (l0 - 1);
            #pragma unroll
            for (int i = 0; i < 5; i++) {
                int c = lane + (i << 5);
                int gl = l0 - 1 + c;
                rx[i] = (c < 130 && gl >= 0 && gl < LEN) ? xrow[c] : 0.f;
            }
            const float* wp = w + (size_t)(co0 + wco_ld) * (CH * 3)
                            + (ci0 + 8) * 3 + wr_ld;
            #pragma unroll
            for (int i = 0; i < 6; i++) rw[i] = wp[i];
        }

        // ---- compute chunk from smem ----
        #pragma unroll
        for (int t = 0; t < 3; t++) {
            uint32_t ah[4], al[4];
            const int r0 = tg * 3 + t;
            ah[0] = Wh[r0     ][wco + g    ]; al[0] = Wl[r0     ][wco + g    ];
            ah[1] = Wh[r0     ][wco + g + 8]; al[1] = Wl[r0     ][wco + g + 8];
            ah[2] = Wh[r0 + 12][wco + g    ]; al[2] = Wl[r0 + 12][wco + g    ];
            ah[3] = Wh[r0 + 12][wco + g + 8]; al[3] = Wl[r0 + 12][wco + g + 8];
            #pragma unroll
            for (int a2 = 0; a2 < 8; a2++) {
                const int c = wpos + (a2 << 3) + g + t;
                uint32_t bh0 = Xh[tg    ][c];
                uint32_t bh1 = Xh[tg + 4][c];
                mma_tf32(acc[a2], ah, bh0, bh1);
                mma_tf32(acc[a2], al, bh0, bh1);
                if (SPLITX) {
                    uint32_t bl0 = Xl[tg    ][c];
                    uint32_t bl1 = Xl[tg + 4][c];
                    mma_tf32(acc[a2], ah, bl0, bl1);
                }
            }
        }
        __syncthreads();
    }

    const int row = co0 + wco + g;
    const float bv0 = bias[row], bv1 = bias[row + 8];
    float* y0 = y + ((size_t)b * CH + row) * LEN + l0 + wpos + (tg << 1);
    #pragma unroll
    for (int a2 = 0; a2 < 8; a2++) {
        *(float2*)(y0 + (a2 << 3)) =
            make_float2(acc[a2].x + bv0, acc[a2].y + bv0);
        *(float2*)(y0 + (size_t)8 * LEN + (a2 << 3)) =
            make_float2(acc[a2].z + bv1, acc[a2].w + bv1);
    }
}

__global__ __launch_bounds__(256)
void conv_qkv_k(const float* __restrict__ q, const float* __restrict__ k,
                const float* __restrict__ v,
                const float* __restrict__ wq, const float* __restrict__ wk,
                const float* __restrict__ wv,
                const float* __restrict__ bq, const float* __restrict__ bk,
                const float* __restrict__ bv,
                float* __restrict__ yq, float* __restrict__ yk,
                float* __restrict__ yv)
{
    int sel = blockIdx.z >> 2, b = blockIdx.z & 3;
    const float* x; const float* w; const float* bia; float* y;
    if (sel == 0)      { x = q; w = wq; bia = bq; y = yq; }
    else if (sel == 1) { x = k; w = wk; bia = bk; y = yk; }
    else               { x = v; w = wv; bia = bv; y = yv; }
    conv_body<false>(x, w, bia, y, b, blockIdx.y << 6, blockIdx.x << 7);
}

__global__ __launch_bounds__(256)
void conv1d_k(const float* __restrict__ x, const float* __restrict__ w,
              const float* __restrict__ bias, float* __restrict__ y)
{
    conv_body<true>(x, w, bias, y, blockIdx.z, blockIdx.y << 6, blockIdx.x << 7);
}

// ---------------------------------------------------------------------------
// Flash attention on tensor cores (single-pass tf32).
// Block = (64-query tile, h, b); 128 threads = 4 warps; warp owns 16 rows.
// Torch-faithful reshape: A[b,h,n,d] = conv[b, n>>2, (n&3)*512 + h*64 + d].
// ---------------------------------------------------------------------------
#define KP_PITCH 68
#define V_PITCH  72

__global__ __launch_bounds__(128)
void attn_k(const float* __restrict__ yq, const float* __restrict__ yk,
            const float* __restrict__ yv, float* __restrict__ z)
{
    __shared__ uint32_t KP[64 * KP_PITCH];  // K tf32 [j][d] -> P tf32 [row][j]
    __shared__ uint32_t Vs[64 * V_PITCH];   // V tf32 [j][d]

    const int tid  = threadIdx.x;
    const int lane = tid & 31;
    const int wid  = tid >> 5;
    const int g    = lane >> 2;
    const int tg   = lane & 3;
    const int m0   = wid << 4;

    const int b = blockIdx.z, h = blockIdx.y;
    const int t0 = blockIdx.x << 6;
    const size_t bbase = (size_t)b * (CH * LEN);
    const int hoff = h << 6;

#define AOFF(n) (bbase + (size_t)((n) >> 2) * LEN + ((n) & 3) * 512 + hoff)

    uint32_t qa[8][4];
    {
        const float* q0 = yq + AOFF(t0 + m0 + g);
        const float* q1 = yq + AOFF(t0 + m0 + g + 8);
        #pragma unroll
        for (int kt = 0; kt < 8; kt++) {
            qa[kt][0] = tf32_rna(q0[tg + 8 * kt]);
            qa[kt][1] = tf32_rna(q1[tg + 8 * kt]);
            qa[kt][2] = tf32_rna(q0[tg + 4 + 8 * kt]);
            qa[kt][3] = tf32_rna(q1[tg + 4 + 8 * kt]);
        }
    }

    float mrow[2] = {-INFINITY, -INFINITY};
    float lrow[2] = {0.f, 0.f};
    float4 o[8];
    #pragma unroll
    for (int nt = 0; nt < 8; nt++) o[nt] = make_float4(0.f, 0.f, 0.f, 0.f);

    for (int j0 = 0; j0 < LEN; j0 += 64) {
        __syncthreads();
        for (int i = tid; i < 1024; i += 128) {
            int r = i >> 4, c4 = (i & 15) << 2;
            size_t off = AOFF(j0 + r) + c4;
            float4 kk = *(const float4*)(yk + off);
            float4 vv = *(const float4*)(yv + off);
            uint4 ku = make_uint4(tf32_rna(kk.x), tf32_rna(kk.y),
                                  tf32_rna(kk.z), tf32_rna(kk.w));
            uint4 vu = make_uint4(tf32_rna(vv.x), tf32_rna(vv.y),
                                  tf32_rna(vv.z), tf32_rna(vv.w));
            *(uint4*)&KP[r * KP_PITCH + c4] = ku;
            *(uint4*)&Vs[r * V_PITCH  + c4] = vu;
        }
        __syncthreads();

        float4 sA[8];
        #pragma unroll
        for (int nt = 0; nt < 8; nt++) sA[nt] = make_float4(0.f, 0.f, 0.f, 0.f);
        #pragma unroll
        for (int kt = 0; kt < 8; kt++) {
            #pragma unroll
            for (int nt = 0; nt < 8; nt++) {
                uint32_t b0 = KP[(nt * 8 + g) * KP_PITCH + tg + 8 * kt];
                uint32_t b1 = KP[(nt * 8 + g) * KP_PITCH + tg + 4 + 8 * kt];
                mma_tf32(sA[nt], qa[kt], b0, b1);
            }
        }
        __syncthreads();

        const float scale = 1.f / 64.f;
        float mx0 = -INFINITY, mx1 = -INFINITY;
        #pragma unroll
        for (int nt = 0; nt < 8; nt++) {
            mx0 = fmaxf(mx0, fmaxf(sA[nt].x, sA[nt].y));
            mx1 = fmaxf(mx1, fmaxf(sA[nt].z, sA[nt].w));
        }
        mx0 *= scale; mx1 *= scale;
        mx0 = fmaxf(mx0, __shfl_xor_sync(0xffffffffu, mx0, 1));
        mx0 = fmaxf(mx0, __shfl_xor_sync(0xffffffffu, mx0, 2));
        mx1 = fmaxf(mx1, __shfl_xor_sync(0xffffffffu, mx1, 1));
        mx1 = fmaxf(mx1, __shfl_xor_sync(0xffffffffu, mx1, 2));
        float nm0 = fmaxf(mrow[0], mx0);
        float nm1 = fmaxf(mrow[1], mx1);
        float corr0 = __expf(mrow[0] - nm0);
        float corr1 = __expf(mrow[1] - nm1);
        mrow[0] = nm0; mrow[1] = nm1;

        float rs0 = 0.f, rs1 = 0.f;
        uint32_t* Prow0 = &KP[(m0 + g)     * KP_PITCH + (tg << 1)];
        uint32_t* Prow1 = &KP[(m0 + g + 8) * KP_PITCH + (tg << 1)];
        #pragma unroll
        for (int nt = 0; nt < 8; nt++) {
            float p00 = __expf(sA[nt].x * scale - nm0);
            float p01 = __expf(sA[nt].y * scale - nm0);
            float p10 = __expf(sA[nt].z * scale - nm1);
            float p11 = __expf(sA[nt].w * scale - nm1);
            rs0 += p00 + p01;
            rs1 += p10 + p11;
            Prow0[nt * 8 + 0] = tf32_rna(p00);
            Prow0[nt * 8 + 1] = tf32_rna(p01);
            Prow1[nt * 8 + 0] = tf32_rna(p10);
            Prow1[nt * 8 + 1] = tf32_rna(p11);
            o[nt].x *= corr0; o[nt].y *= corr0;
            o[nt].z *= corr1; o[nt].w *= corr1;
        }
        rs0 += __shfl_xor_sync(0xffffffffu, rs0, 1);
        rs0 += __shfl_xor_sync(0xffffffffu, rs0, 2);
        rs1 += __shfl_xor_sync(0xffffffffu, rs1, 1);
        rs1 += __shfl_xor_sync(0xffffffffu, rs1, 2);
        lrow[0] = lrow[0] * corr0 + rs0;
        lrow[1] = lrow[1] * corr1 + rs1;
        __syncwarp();

        #pragma unroll
        for (int kt = 0; kt < 8; kt++) {
            uint32_t pa[4];
            pa[0] = KP[(m0 + g)     * KP_PITCH + tg + 8 * kt];
            pa[1] = KP[(m0 + g + 8) * KP_PITCH + tg + 8 * kt];
            pa[2] = KP[(m0 + g)     * KP_PITCH + tg + 4 + 8 * kt];
            pa[3] = KP[(m0 + g + 8) * KP_PITCH + tg + 4 + 8 * kt];
            #pragma unroll
            for (int nt = 0; nt < 8; nt++) {
                uint32_t b0 = Vs[(tg + 8 * kt)     * V_PITCH + nt * 8 + g];
                uint32_t b1 = Vs[(tg + 4 + 8 * kt) * V_PITCH + nt * 8 + g];
                mma_tf32(o[nt], pa, b0, b1);
            }
        }
    }

    const float inv0 = 1.f / lrow[0];
    const float inv1 = 1.f / lrow[1];
    float* z0 = z + AOFF(t0 + m0 + g)     + (tg << 1);
    float* z1 = z + AOFF(t0 + m0 + g + 8) + (tg << 1);
    #pragma unroll
    for (int nt = 0; nt < 8; nt++) {
        *(float2*)(z0 + nt * 8) = make_float2(o[nt].x * inv0, o[nt].y * inv0);
        *(float2*)(z1 + nt * 8) = make_float2(o[nt].z * inv1, o[nt].w * inv1);
    }
#undef AOFF
}

// ---------------------------------------------------------------------------
extern "C" void kernel_launch(void* const* d_in, const int* in_sizes, int n_in,
                              void* d_out, int out_size)
{
    const float* q    = (const float*)d_in[0];
    const float* k    = (const float*)d_in[1];
    const float* v    = (const float*)d_in[2];
    const float* wq_w = (const float*)d_in[3];
    const float* wq_b = (const float*)d_in[4];
    const float* wk_w = (const float*)d_in[5];
    const float* wk_b = (const float*)d_in[6];
    const float* wv_w = (const float*)d_in[7];
    const float* wv_b = (const float*)d_in[8];
    const float* fc_w = (const float*)d_in[9];
    const float* fc_b = (const float*)d_in[10];
    float* out = (float*)d_out;

    float *yq, *yk, *yv, *zb;
    cudaGetSymbolAddress((void**)&yq, g_yq);
    cudaGetSymbolAddress((void**)&yk, g_yk);
    cudaGetSymbolAddress((void**)&yv, g_yv);
    cudaGetSymbolAddress((void**)&zb, g_z);

    dim3 gqkv(LEN / 128, CH / 64, 3 * BATCH);   // (16, 8, 12)
    conv_qkv_k<<<gqkv, 256>>>(q, k, v, wq_w, wk_w, wv_w, wq_b, wk_b, wv_b,
                              yq, yk, yv);

    dim3 agrid(LEN / 64, 8, BATCH);             // (32, 8, 4)
    attn_k<<<agrid, 128>>>(yq, yk, yv, zb);

    dim3 gfc(LEN / 128, CH / 64, BATCH);        // (16, 8, 4)
    conv1d_k<<<gfc, 256>>>(zb, fc_w, fc_b, out);
}